// round 8
// baseline (speedup 1.0000x reference)
#include <cuda_runtime.h>

#define BB 2048
#define TT 1024
#define DD 64
#define HH 16
#define NW 8               // warps per K1 block
#define CH 128             // timesteps per K1 warp
#define GB 16              // batches per K2 warp
#define INV_TAU (1.0f/6.0f)

typedef unsigned long long u64;

// xw scratch: [B, T, 16]
__device__ float g_xw[(size_t)BB * TT * HH];

__device__ __forceinline__ u64 pk2(float lo, float hi) {
    u64 r; asm("mov.b64 %0, {%1,%2};" : "=l"(r) : "f"(lo), "f"(hi)); return r;
}
__device__ __forceinline__ u64 mul2(u64 a, u64 b) {
    u64 r; asm("mul.rn.f32x2 %0, %1, %2;" : "=l"(r) : "l"(a), "l"(b)); return r;
}
__device__ __forceinline__ u64 fma2(u64 a, u64 b, u64 c) {
    u64 r; asm("fma.rn.f32x2 %0, %1, %2, %3;" : "=l"(r) : "l"(a), "l"(b), "l"(c)); return r;
}
__device__ __forceinline__ u64 add2(u64 a, u64 b) {
    u64 r; asm("add.rn.f32x2 %0, %1, %2;" : "=l"(r) : "l"(a), "l"(b)); return r;
}
__device__ __forceinline__ float hadd2(u64 a) {
    float lo, hi; asm("mov.b64 {%0,%1}, %2;" : "=f"(lo), "=f"(hi) : "l"(a)); return lo + hi;
}
__device__ __forceinline__ void unpk2(u64 a, float& lo, float& hi) {
    asm("mov.b64 {%0,%1}, %2;" : "=f"(lo), "=f"(hi) : "l"(a));
}

// exp(-k) for k in [1/6, 2/3): degree-5 poly about c=5/12. rel err ~4e-7.
__device__ __forceinline__ float expnk(float k) {
    const float E = 0.6592406302004438f;         // exp(-5/12)
    float x = k - 0.4166666666666667f;
    float p = -E / 120.0f;
    p = fmaf(p, x,  E / 24.0f);
    p = fmaf(p, x, -E / 6.0f);
    p = fmaf(p, x,  E * 0.5f);
    p = fmaf(p, x, -E);
    p = fmaf(p, x,  E);
    return p;
}

// ============================================================================
// K1: synaptic chunk-scan + x_cat + input projection -> g_xw  (R6 version)
// Block = 256 threads (8 warps) = one batch. Warp w owns t in [128w, 128w+128).
// ============================================================================
__global__ void __launch_bounds__(256, 2) k1_syn_proj(
    const float* __restrict__ inputs,   // [B,T,64]
    const float* __restrict__ syn_x0,   // [B,64]
    const float* __restrict__ w_ih,     // [128,16]
    float* __restrict__ out_xcat)       // [B,T,128]
{
    __shared__ float wsm[2*DD][HH];     // raw copy of w_ih
    __shared__ float Asm[NW][DD];
    __shared__ float Bsm[NW][DD];
    __shared__ float Ssm[NW][DD];

    const int b    = blockIdx.x;
    const int tid  = threadIdx.x;
    const int w    = tid >> 5;
    const int lane = tid & 31;
    const int t0   = w * CH;

    {
        const float4* src = reinterpret_cast<const float4*>(w_ih);
        float4* dst = reinterpret_cast<float4*>(&wsm[0][0]);
        for (int i = tid; i < 2*DD*HH/4; i += 256) dst[i] = src[i];
    }
    __syncthreads();

    u64 wa0[8], wa1[8], wb0[8], wb1[8];
#pragma unroll
    for (int i = 0; i < 8; i++) {
        wa0[i] = *reinterpret_cast<const u64*>(&wsm[2*lane   ][2*i]);
        wa1[i] = *reinterpret_cast<const u64*>(&wsm[2*lane+1 ][2*i]);
        wb0[i] = *reinterpret_cast<const u64*>(&wsm[64+2*lane][2*i]);
        wb1[i] = *reinterpret_cast<const u64*>(&wsm[65+2*lane][2*i]);
    }

    const float2* ip = reinterpret_cast<const float2*>(inputs)
                       + ((size_t)b*TT + t0)*(DD/2) + lane;

    // ---- phase 1: compose chunk affine (A,B) per owned d ----
    {
        float2 A  = make_float2(1.f, 1.f);
        float2 Bc = make_float2(0.f, 0.f);
        float2 buf[4];
#pragma unroll
        for (int k = 0; k < 4; k++) buf[k] = ip[k*(DD/2)];
        for (int t = 0; t < CH; t++) {
            float2 in = buf[t & 3];
            if (t + 4 < CH) buf[t & 3] = ip[(t + 4)*(DD/2)];
            float kx = fmaf(0.5f, in.x, INV_TAU);
            float ky = fmaf(0.5f, in.y, INV_TAU);
            float ex = expnk(kx);
            float ey = expnk(ky);
            float rx = __fdividef(INV_TAU, kx);
            float ry = __fdividef(INV_TAU, ky);
            float bx = fmaf(-rx, ex, rx);
            float by = fmaf(-ry, ey, ry);
            A.x *= ex;  A.y *= ey;
            Bc.x = fmaf(ex, Bc.x, bx);
            Bc.y = fmaf(ey, Bc.y, by);
        }
        *reinterpret_cast<float2*>(&Asm[w][2*lane]) = A;
        *reinterpret_cast<float2*>(&Bsm[w][2*lane]) = Bc;
    }
    __syncthreads();

    // ---- phase 2: exclusive block scan over 8 chunks ----
    if (tid < DD) {
        float s = syn_x0[b*DD + tid];
#pragma unroll
        for (int c = 0; c < NW; c++) {
            Ssm[c][tid] = s;
            s = fmaf(Asm[c][tid], s, Bsm[c][tid]);
        }
    }
    __syncthreads();

    // ---- phase 3: re-stream, emit x_cat + xw ----
    float2 s = *reinterpret_cast<float2*>(&Ssm[w][2*lane]);
    float2* xc = reinterpret_cast<float2*>(out_xcat)
                 + ((size_t)b*TT + t0)*DD + lane;
    float* xwp = g_xw + ((size_t)b*TT + t0)*HH;
    const int hsel = ((lane & 1) << 3) | ((lane & 2) << 1)
                   | ((lane & 4) >> 1) | ((lane & 8) >> 3);

    float2 buf[4];
#pragma unroll
    for (int k = 0; k < 4; k++) buf[k] = ip[k*(DD/2)];

    for (int t = 0; t < CH; t++) {
        float2 in = buf[t & 3];
        if (t + 4 < CH) buf[t & 3] = ip[(t + 4)*(DD/2)];

        float kx = fmaf(0.5f, in.x, INV_TAU);
        float ky = fmaf(0.5f, in.y, INV_TAU);
        float ex = expnk(kx);
        float ey = expnk(ky);
        float rx = __fdividef(INV_TAU, kx);
        float ry = __fdividef(INV_TAU, ky);

        float2 sx;
        sx.x = s.x * in.x;
        sx.y = s.y * in.y;

        xc[t*DD]      = in;
        xc[t*DD + 32] = sx;

        float bx = fmaf(-rx, ex, rx);
        float by = fmaf(-ry, ey, ry);
        s.x = fmaf(ex, s.x, bx);
        s.y = fmaf(ey, s.y, by);

        u64 dx0 = pk2(in.x, in.x);
        u64 dx1 = pk2(in.y, in.y);
        u64 ds0 = pk2(sx.x, sx.x);
        u64 ds1 = pk2(sx.y, sx.y);
        u64 acc[8];
#pragma unroll
        for (int i = 0; i < 8; i++) {
            u64 a = mul2(dx0, wa0[i]);
            a = fma2(dx1, wa1[i], a);
            a = fma2(ds0, wb0[i], a);
            a = fma2(ds1, wb1[i], a);
            acc[i] = a;
        }

        u64 q4[4];
        {
            bool lo = (lane & 1) == 0;
#pragma unroll
            for (int i = 0; i < 4; i++) {
                u64 send = lo ? acc[4 + i] : acc[i];
                u64 recv = __shfl_xor_sync(0xffffffffu, send, 1);
                q4[i] = add2(lo ? acc[i] : acc[4 + i], recv);
            }
        }
        u64 q2[2];
        {
            bool lo = (lane & 2) == 0;
#pragma unroll
            for (int i = 0; i < 2; i++) {
                u64 send = lo ? q4[2 + i] : q4[i];
                u64 recv = __shfl_xor_sync(0xffffffffu, send, 2);
                q2[i] = add2(lo ? q4[i] : q4[2 + i], recv);
            }
        }
        u64 q1;
        {
            bool lo = (lane & 4) == 0;
            u64 send = lo ? q2[1] : q2[0];
            u64 recv = __shfl_xor_sync(0xffffffffu, send, 4);
            q1 = add2(lo ? q2[0] : q2[1], recv);
        }
        float xwv;
        {
            float a, bb;
            unpk2(q1, a, bb);
            bool lo = (lane & 8) == 0;
            float send = lo ? bb : a;
            float recv = __shfl_xor_sync(0xffffffffu, send, 8);
            xwv = (lo ? a : bb) + recv;
            xwv += __shfl_xor_sync(0xffffffffu, xwv, 16);
        }

        if (lane < HH) xwp[t*HH + hsel] = xwv;
    }
}

// ============================================================================
// K2: sequential ReLU RNN + hidden + output. 16 batches per warp.
// Grid = 128 single-warp blocks. Lane = (batch bb = lane&15, h-half hf = lane>>4).
// Lane keeps h[8hf..8hf+7] of its batch; partner half arrives via 8 shfl-xor16.
// Matvec: 64 fma.rn.f32x2 per lane per t (16 batches' full 16x16 matvec/warp).
// ============================================================================
__global__ void __launch_bounds__(32, 1) k2_rnn(
    const float* __restrict__ h0,       // [B,16]
    const float* __restrict__ w_hh,     // [16,16]
    const float* __restrict__ bias,     // [16]
    const float* __restrict__ lin_w,    // [16]
    const float* __restrict__ lin_b,    // [1]
    float* __restrict__ out_output,     // [B,T]
    float* __restrict__ out_hidden)     // [B,T,16]
{
    const int lane = threadIdx.x;
    const int bb   = lane & 15;
    const int hf   = lane >> 4;          // which h-half this lane owns
    const int b    = blockIdx.x * GB + bb;
    const int jb   = hf * 8;             // base j of own half

    // weights: wo[k][m] = (W[jb_own_i + k][jb+2m], W[..][jb+2m+1]) — own-i rows first,
    // then wp[k][m] for partner-i rows. u64 loads (j-pairs contiguous in w_hh rows).
    u64 wo[8][4], wp[8][4];
#pragma unroll
    for (int k = 0; k < 8; k++) {
#pragma unroll
        for (int m = 0; m < 4; m++) {
            wo[k][m] = *reinterpret_cast<const u64*>(&w_hh[(jb + k)*HH + jb + 2*m]);
            wp[k][m] = *reinterpret_cast<const u64*>(&w_hh[((8 - jb) + k)*HH + jb + 2*m]);
        }
    }
    u64 biasP[4];
#pragma unroll
    for (int m = 0; m < 4; m++)
        biasP[m] = *reinterpret_cast<const u64*>(&bias[jb + 2*m]);
    float lwS[8];
#pragma unroll
    for (int k = 0; k < 8; k++) lwS[k] = lin_w[jb + k];
    const float lb = lin_b[0];

    // state: own h-half as scalars
    float h[8];
    {
        float4 a = *reinterpret_cast<const float4*>(&h0[b*HH + jb]);
        float4 c = *reinterpret_cast<const float4*>(&h0[b*HH + jb + 4]);
        h[0]=a.x; h[1]=a.y; h[2]=a.z; h[3]=a.w;
        h[4]=c.x; h[5]=c.y; h[6]=c.z; h[7]=c.w;
    }

    const float* xp = g_xw + (size_t)b*TT*HH + jb;      // own half of xw row
    float*      hid = out_hidden + (size_t)b*TT*HH + jb;
    float*       op = out_output + (size_t)b*TT;

    // prefetch ring (depth 4) of own 32B xw slice
    float4 ra[4], rb[4];
#pragma unroll
    for (int p = 0; p < 4; p++) {
        ra[p] = *reinterpret_cast<const float4*>(&xp[p*HH]);
        rb[p] = *reinterpret_cast<const float4*>(&xp[p*HH + 4]);
    }

    for (int t = 0; t < TT; t++) {
        float4 xa = ra[t & 3], xb = rb[t & 3];
        if (t + 4 < TT) {
            ra[t & 3] = *reinterpret_cast<const float4*>(&xp[(t + 4)*HH]);
            rb[t & 3] = *reinterpret_cast<const float4*>(&xp[(t + 4)*HH + 4]);
        }

        // partner's h-half (8 shfl; overlapped by own-half fma below)
        float ph[8];
#pragma unroll
        for (int k = 0; k < 8; k++)
            ph[k] = __shfl_xor_sync(0xffffffffu, h[k], 16);

        // acc init: xw(own j-half) + bias
        u64 acc[4];
        acc[0] = add2(pk2(xa.x, xa.y), biasP[0]);
        acc[1] = add2(pk2(xa.z, xa.w), biasP[1]);
        acc[2] = add2(pk2(xb.x, xb.y), biasP[2]);
        acc[3] = add2(pk2(xb.z, xb.w), biasP[3]);

        // own-i contributions (i = jb + k)
#pragma unroll
        for (int k = 0; k < 8; k++) {
            u64 hd = pk2(h[k], h[k]);
            acc[0] = fma2(hd, wo[k][0], acc[0]);
            acc[1] = fma2(hd, wo[k][1], acc[1]);
            acc[2] = fma2(hd, wo[k][2], acc[2]);
            acc[3] = fma2(hd, wo[k][3], acc[3]);
        }
        // partner-i contributions (i = (8-jb) + k)
#pragma unroll
        for (int k = 0; k < 8; k++) {
            u64 hd = pk2(ph[k], ph[k]);
            acc[0] = fma2(hd, wp[k][0], acc[0]);
            acc[1] = fma2(hd, wp[k][1], acc[1]);
            acc[2] = fma2(hd, wp[k][2], acc[2]);
            acc[3] = fma2(hd, wp[k][3], acc[3]);
        }

        // relu -> new own h-half
#pragma unroll
        for (int m = 0; m < 4; m++) {
            float e0, e1;
            unpk2(acc[m], e0, e1);
            h[2*m]     = fmaxf(e0, 0.0f);
            h[2*m + 1] = fmaxf(e1, 0.0f);
        }

        // hidden store: 2x STG.128, 64B per (b,t) cell across the lane pair
        {
            float4 v0 = make_float4(h[0], h[1], h[2], h[3]);
            float4 v1 = make_float4(h[4], h[5], h[6], h[7]);
            *reinterpret_cast<float4*>(&hid[t*HH])     = v0;
            *reinterpret_cast<float4*>(&hid[t*HH + 4]) = v1;
        }

        // output: dot(h_t, lin_w) + lb; halves combine via xor16
        float v0 = h[0]*lwS[0] + h[1]*lwS[1];
        float v1 = h[2]*lwS[2] + h[3]*lwS[3];
        v0 = fmaf(h[4], lwS[4], v0);
        v1 = fmaf(h[5], lwS[5], v1);
        v0 = fmaf(h[6], lwS[6], v0);
        v1 = fmaf(h[7], lwS[7], v1);
        float v = v0 + v1;
        v += __shfl_xor_sync(0xffffffffu, v, 16);
        if (hf == 0) op[t] = v + lb;
    }
}

extern "C" void kernel_launch(void* const* d_in, const int* in_sizes, int n_in,
                              void* d_out, int out_size) {
    const float* inputs = (const float*)d_in[0];   // [B,T,64]
    const float* syn_x0 = (const float*)d_in[1];   // [B,64]
    const float* h0     = (const float*)d_in[2];   // [B,16]
    const float* w_ih   = (const float*)d_in[3];   // [128,16]
    const float* w_hh   = (const float*)d_in[4];   // [16,16]
    const float* bias   = (const float*)d_in[5];   // [16]
    const float* lin_w  = (const float*)d_in[6];   // [16,1]
    const float* lin_b  = (const float*)d_in[7];   // [1]

    float* out = (float*)d_out;
    // tuple concat order: output [B,T,1], hidden [B,T,16], x_cat [B,T,128]
    float* out_output = out;
    float* out_hidden = out + (size_t)BB*TT;
    float* out_xcat   = out + (size_t)BB*TT + (size_t)BB*TT*HH;

    k1_syn_proj<<<BB, 256>>>(inputs, syn_x0, w_ih, out_xcat);
    k2_rnn<<<BB/GB, 32>>>(h0, w_hh, bias, lin_w, lin_b, out_output, out_hidden);
}

// round 9
// speedup vs baseline: 1.6421x; 1.6421x over previous
#include <cuda_runtime.h>

#define BB 2048
#define TT 1024
#define DD 64
#define HH 16
#define NW 8               // warps per K1 block
#define CH 128             // timesteps per K1 warp
#define INV_TAU (1.0f/6.0f)

typedef unsigned long long u64;

// xw scratch: [B, T, 16]
__device__ float g_xw[(size_t)BB * TT * HH];

__device__ __forceinline__ u64 pk2(float lo, float hi) {
    u64 r; asm("mov.b64 %0, {%1,%2};" : "=l"(r) : "f"(lo), "f"(hi)); return r;
}
__device__ __forceinline__ u64 mul2(u64 a, u64 b) {
    u64 r; asm("mul.rn.f32x2 %0, %1, %2;" : "=l"(r) : "l"(a), "l"(b)); return r;
}
__device__ __forceinline__ u64 fma2(u64 a, u64 b, u64 c) {
    u64 r; asm("fma.rn.f32x2 %0, %1, %2, %3;" : "=l"(r) : "l"(a), "l"(b), "l"(c)); return r;
}
__device__ __forceinline__ u64 add2(u64 a, u64 b) {
    u64 r; asm("add.rn.f32x2 %0, %1, %2;" : "=l"(r) : "l"(a), "l"(b)); return r;
}

// exp(-k) for k in [1/6, 2/3): degree-5 poly about c=5/12. rel err ~4e-7.
__device__ __forceinline__ float expnk(float k) {
    const float E = 0.6592406302004438f;         // exp(-5/12)
    float x = k - 0.4166666666666667f;
    float p = -E / 120.0f;
    p = fmaf(p, x,  E / 24.0f);
    p = fmaf(p, x, -E / 6.0f);
    p = fmaf(p, x,  E * 0.5f);
    p = fmaf(p, x, -E);
    p = fmaf(p, x,  E);
    return p;
}

// ============================================================================
// K1: synaptic chunk-scan + x_cat + input projection -> g_xw
// Block = 256 threads (8 warps) = one batch. Warp w owns t in [128w, 128w+128).
// Lane owns d-pair (2l, 2l+1). Select-free XOR-permuted butterfly:
// slot i of lane l accumulates h-pair (i ^ sig(l)); every stage is a plain
// shfl_xor + add2. Lanes 0-7 end with complete pair sig(l), store STG.64.
// ============================================================================
__global__ void __launch_bounds__(256, 2) k1_syn_proj(
    const float* __restrict__ inputs,   // [B,T,64]
    const float* __restrict__ syn_x0,   // [B,64]
    const float* __restrict__ w_ih,     // [128,16]
    float* __restrict__ out_xcat)       // [B,T,128]
{
    __shared__ float wsm[2*DD][HH];     // raw copy of w_ih
    __shared__ float Asm[NW][DD];
    __shared__ float Bsm[NW][DD];
    __shared__ float Ssm[NW][DD];

    const int b    = blockIdx.x;
    const int tid  = threadIdx.x;
    const int w    = tid >> 5;
    const int lane = tid & 31;
    const int t0   = w * CH;
    // slot permutation: sig(l^1)=sig^4, sig(l^2)=sig^2, sig(l^4)=sig^1
    const int sig  = ((lane & 1) << 2) | (lane & 2) | ((lane >> 2) & 1);

    {
        const float4* src = reinterpret_cast<const float4*>(w_ih);
        float4* dst = reinterpret_cast<float4*>(&wsm[0][0]);
        for (int i = tid; i < 2*DD*HH/4; i += 256) dst[i] = src[i];
    }
    __syncthreads();

    // slot i holds weights for h-pair p = i ^ sig
    u64 wa0[8], wa1[8], wb0[8], wb1[8];
#pragma unroll
    for (int i = 0; i < 8; i++) {
        const int p = i ^ sig;
        wa0[i] = *reinterpret_cast<const u64*>(&wsm[2*lane   ][2*p]);
        wa1[i] = *reinterpret_cast<const u64*>(&wsm[2*lane+1 ][2*p]);
        wb0[i] = *reinterpret_cast<const u64*>(&wsm[64+2*lane][2*p]);
        wb1[i] = *reinterpret_cast<const u64*>(&wsm[65+2*lane][2*p]);
    }

    const float2* ip = reinterpret_cast<const float2*>(inputs)
                       + ((size_t)b*TT + t0)*(DD/2) + lane;

    // ---- phase 1: compose chunk affine (A,B) per owned d ----
    {
        float2 A  = make_float2(1.f, 1.f);
        float2 Bc = make_float2(0.f, 0.f);
        float2 buf[4];
#pragma unroll
        for (int k = 0; k < 4; k++) buf[k] = ip[k*(DD/2)];
        for (int t = 0; t < CH; t++) {
            float2 in = buf[t & 3];
            if (t + 4 < CH) buf[t & 3] = ip[(t + 4)*(DD/2)];
            float kx = fmaf(0.5f, in.x, INV_TAU);
            float ky = fmaf(0.5f, in.y, INV_TAU);
            float ex = expnk(kx);
            float ey = expnk(ky);
            float rx = __fdividef(INV_TAU, kx);
            float ry = __fdividef(INV_TAU, ky);
            float bx = fmaf(-rx, ex, rx);
            float by = fmaf(-ry, ey, ry);
            A.x *= ex;  A.y *= ey;
            Bc.x = fmaf(ex, Bc.x, bx);
            Bc.y = fmaf(ey, Bc.y, by);
        }
        *reinterpret_cast<float2*>(&Asm[w][2*lane]) = A;
        *reinterpret_cast<float2*>(&Bsm[w][2*lane]) = Bc;
    }
    __syncthreads();

    // ---- phase 2: exclusive block scan over 8 chunks ----
    if (tid < DD) {
        float s = syn_x0[b*DD + tid];
#pragma unroll
        for (int c = 0; c < NW; c++) {
            Ssm[c][tid] = s;
            s = fmaf(Asm[c][tid], s, Bsm[c][tid]);
        }
    }
    __syncthreads();

    // ---- phase 3: re-stream, emit x_cat + xw ----
    float2 s = *reinterpret_cast<float2*>(&Ssm[w][2*lane]);
    float2* xc = reinterpret_cast<float2*>(out_xcat)
                 + ((size_t)b*TT + t0)*DD + lane;
    float* xwp = g_xw + ((size_t)b*TT + t0)*HH;

    float2 buf[4];
#pragma unroll
    for (int k = 0; k < 4; k++) buf[k] = ip[k*(DD/2)];

    for (int t = 0; t < CH; t++) {
        float2 in = buf[t & 3];
        if (t + 4 < CH) buf[t & 3] = ip[(t + 4)*(DD/2)];

        float kx = fmaf(0.5f, in.x, INV_TAU);
        float ky = fmaf(0.5f, in.y, INV_TAU);
        float ex = expnk(kx);
        float ey = expnk(ky);
        float rx = __fdividef(INV_TAU, kx);
        float ry = __fdividef(INV_TAU, ky);

        float2 sx;
        sx.x = s.x * in.x;
        sx.y = s.y * in.y;

        xc[t*DD]      = in;
        xc[t*DD + 32] = sx;

        float bx = fmaf(-rx, ex, rx);
        float by = fmaf(-ry, ey, ry);
        s.x = fmaf(ex, s.x, bx);
        s.y = fmaf(ey, s.y, by);

        // slot i accumulates h-pair (i ^ sig) over this lane's 2 d's
        u64 dx0 = pk2(in.x, in.x);
        u64 dx1 = pk2(in.y, in.y);
        u64 ds0 = pk2(sx.x, sx.x);
        u64 ds1 = pk2(sx.y, sx.y);
        u64 acc[8];
#pragma unroll
        for (int i = 0; i < 8; i++) {
            u64 a = mul2(dx0, wa0[i]);
            a = fma2(dx1, wa1[i], a);
            a = fma2(ds0, wb0[i], a);
            a = fma2(ds1, wb1[i], a);
            acc[i] = a;
        }

        // select-free butterfly: plain shfl_xor + add2 at every stage
#pragma unroll
        for (int i = 0; i < 4; i++)
            acc[i] = add2(acc[i], __shfl_xor_sync(0xffffffffu, acc[i + 4], 1));
#pragma unroll
        for (int i = 0; i < 2; i++)
            acc[i] = add2(acc[i], __shfl_xor_sync(0xffffffffu, acc[i + 2], 2));
        acc[0] = add2(acc[0], __shfl_xor_sync(0xffffffffu, acc[1], 4));
        acc[0] = add2(acc[0], __shfl_xor_sync(0xffffffffu, acc[0], 8));
        acc[0] = add2(acc[0], __shfl_xor_sync(0xffffffffu, acc[0], 16));

        // lane l (<8) holds complete h-pair sig(l): store u64 (coalesced 64B)
        if (lane < 8)
            *reinterpret_cast<u64*>(&xwp[t*HH + 2*sig]) = acc[0];
    }
}

// ============================================================================
// K2: sequential ReLU RNN + hidden + output. 2 batches per warp.
// Half-warp = batch, lane = h-index j. One shfl with per-lane src serves both
// batches: 8 shfl/batch-t. Matvec + output dot fully local (no reduce shfls);
// output computed one step deferred from the broadcast registers.
// ============================================================================
__global__ void __launch_bounds__(32) k2_rnn(
    const float* __restrict__ h0,       // [B,16]
    const float* __restrict__ w_hh,     // [16,16]
    const float* __restrict__ bias,     // [16]
    const float* __restrict__ lin_w,    // [16]
    const float* __restrict__ lin_b,    // [1]
    float* __restrict__ out_output,     // [B,T]
    float* __restrict__ out_hidden)     // [B,T,16]
{
    const int lane = threadIdx.x;
    const int j    = lane & 15;
    const int base = lane & 16;          // src base for this half's broadcasts
    const int b    = blockIdx.x * 2 + (lane >> 4);

    float wj[HH], lw[HH];
#pragma unroll
    for (int i = 0; i < HH; i++) {
        wj[i] = w_hh[i*HH + j];
        lw[i] = lin_w[i];
    }
    const float biasj = bias[j];
    const float lb    = lin_b[0];

    float h = h0[b*HH + j];              // lane holds h[j] of its batch

    const float* xp = g_xw + (size_t)b*TT*HH + j;
    float*      hid = out_hidden + (size_t)b*TT*HH + j;
    float*       op = out_output + (size_t)b*TT;

    float buf[8];
#pragma unroll
    for (int p = 0; p < 8; p++) buf[p] = xp[p*HH];

    for (int t = 0; t < TT; t++) {
        float xwv = buf[t & 7];
        if (t + 8 < TT) buf[t & 7] = xp[(t + 8)*HH];

        // broadcast h_{t-1} of this half's batch: per-lane src lane
        float hb[HH];
#pragma unroll
        for (int i = 0; i < HH; i++)
            hb[i] = __shfl_sync(0xffffffffu, h, base + i);

        // matvec (two chains)
        float a0 = xwv + biasj, a1 = 0.0f;
#pragma unroll
        for (int i = 0; i < HH; i += 2) {
            a0 = fmaf(hb[i],     wj[i],     a0);
            a1 = fmaf(hb[i + 1], wj[i + 1], a1);
        }
        h = fmaxf(a0 + a1, 0.0f);

        hid[t*HH] = h;                   // both halves store their batch

        // output for step t-1 (local dot of hb = h_{t-1})
        float v0 = 0.0f, v1 = 0.0f;
#pragma unroll
        for (int i = 0; i < HH; i += 2) {
            v0 = fmaf(hb[i],     lw[i],     v0);
            v1 = fmaf(hb[i + 1], lw[i + 1], v1);
        }
        if (j == 0 && t > 0) op[t - 1] = v0 + v1 + lb;
    }

    // epilogue: output for t = TT-1
    {
        float hb[HH];
#pragma unroll
        for (int i = 0; i < HH; i++)
            hb[i] = __shfl_sync(0xffffffffu, h, base + i);
        float v0 = 0.0f, v1 = 0.0f;
#pragma unroll
        for (int i = 0; i < HH; i += 2) {
            v0 = fmaf(hb[i],     lw[i],     v0);
            v1 = fmaf(hb[i + 1], lw[i + 1], v1);
        }
        if (j == 0) op[TT - 1] = v0 + v1 + lb;
    }
}

extern "C" void kernel_launch(void* const* d_in, const int* in_sizes, int n_in,
                              void* d_out, int out_size) {
    const float* inputs = (const float*)d_in[0];   // [B,T,64]
    const float* syn_x0 = (const float*)d_in[1];   // [B,64]
    const float* h0     = (const float*)d_in[2];   // [B,16]
    const float* w_ih   = (const float*)d_in[3];   // [128,16]
    const float* w_hh   = (const float*)d_in[4];   // [16,16]
    const float* bias   = (const float*)d_in[5];   // [16]
    const float* lin_w  = (const float*)d_in[6];   // [16,1]
    const float* lin_b  = (const float*)d_in[7];   // [1]

    float* out = (float*)d_out;
    // tuple concat order: output [B,T,1], hidden [B,T,16], x_cat [B,T,128]
    float* out_output = out;
    float* out_hidden = out + (size_t)BB*TT;
    float* out_xcat   = out + (size_t)BB*TT + (size_t)BB*TT*HH;

    k1_syn_proj<<<BB, 256>>>(inputs, syn_x0, w_ih, out_xcat);
    k2_rnn<<<BB/2, 32>>>(h0, w_hh, bias, lin_w, lin_b, out_output, out_hidden);
}

// round 10
// speedup vs baseline: 1.9077x; 1.1618x over previous
#include <cuda_runtime.h>

#define BB 2048
#define TT 1024
#define DD 64
#define HH 16
#define NW 8               // warps per K1 block
#define CH 128             // timesteps per K1 warp
#define INV_TAU (1.0f/6.0f)

typedef unsigned long long u64;

// xw scratch: [B, T, 16]
__device__ float g_xw[(size_t)BB * TT * HH];

__device__ __forceinline__ u64 pk2(float lo, float hi) {
    u64 r; asm("mov.b64 %0, {%1,%2};" : "=l"(r) : "f"(lo), "f"(hi)); return r;
}
__device__ __forceinline__ u64 mul2(u64 a, u64 b) {
    u64 r; asm("mul.rn.f32x2 %0, %1, %2;" : "=l"(r) : "l"(a), "l"(b)); return r;
}
__device__ __forceinline__ u64 fma2(u64 a, u64 b, u64 c) {
    u64 r; asm("fma.rn.f32x2 %0, %1, %2, %3;" : "=l"(r) : "l"(a), "l"(b), "l"(c)); return r;
}
__device__ __forceinline__ u64 add2(u64 a, u64 b) {
    u64 r; asm("add.rn.f32x2 %0, %1, %2;" : "=l"(r) : "l"(a), "l"(b)); return r;
}

// exp(-k) for k in [1/6, 2/3): degree-5 poly about c=5/12. rel err ~4e-7.
__device__ __forceinline__ float expnk(float k) {
    const float E = 0.6592406302004438f;         // exp(-5/12)
    float x = k - 0.4166666666666667f;
    float p = -E / 120.0f;
    p = fmaf(p, x,  E / 24.0f);
    p = fmaf(p, x, -E / 6.0f);
    p = fmaf(p, x,  E * 0.5f);
    p = fmaf(p, x, -E);
    p = fmaf(p, x,  E);
    return p;
}

// ============================================================================
// K1: synaptic chunk-scan + x_cat + input projection -> g_xw
// Block = 256 threads (8 warps) = one batch. Warp w owns t in [128w, 128w+128).
// Lane owns d-pair (2l, 2l+1). Select-free XOR-permuted butterfly.
// t-loops unrolled by ring depth so prefetch ring stays in registers.
// ============================================================================
__global__ void __launch_bounds__(256, 2) k1_syn_proj(
    const float* __restrict__ inputs,   // [B,T,64]
    const float* __restrict__ syn_x0,   // [B,64]
    const float* __restrict__ w_ih,     // [128,16]
    float* __restrict__ out_xcat)       // [B,T,128]
{
    __shared__ float wsm[2*DD][HH];     // raw copy of w_ih
    __shared__ float Asm[NW][DD];
    __shared__ float Bsm[NW][DD];
    __shared__ float Ssm[NW][DD];

    const int b    = blockIdx.x;
    const int tid  = threadIdx.x;
    const int w    = tid >> 5;
    const int lane = tid & 31;
    const int t0   = w * CH;
    // slot permutation: sig(l^1)=sig^4, sig(l^2)=sig^2, sig(l^4)=sig^1
    const int sig  = ((lane & 1) << 2) | (lane & 2) | ((lane >> 2) & 1);

    {
        const float4* src = reinterpret_cast<const float4*>(w_ih);
        float4* dst = reinterpret_cast<float4*>(&wsm[0][0]);
        for (int i = tid; i < 2*DD*HH/4; i += 256) dst[i] = src[i];
    }
    __syncthreads();

    // slot i holds weights for h-pair p = i ^ sig
    u64 wa0[8], wa1[8], wb0[8], wb1[8];
#pragma unroll
    for (int i = 0; i < 8; i++) {
        const int p = i ^ sig;
        wa0[i] = *reinterpret_cast<const u64*>(&wsm[2*lane   ][2*p]);
        wa1[i] = *reinterpret_cast<const u64*>(&wsm[2*lane+1 ][2*p]);
        wb0[i] = *reinterpret_cast<const u64*>(&wsm[64+2*lane][2*p]);
        wb1[i] = *reinterpret_cast<const u64*>(&wsm[65+2*lane][2*p]);
    }

    const float2* ip = reinterpret_cast<const float2*>(inputs)
                       + ((size_t)b*TT + t0)*(DD/2) + lane;

    // ---- phase 1: compose chunk affine (A,B) per owned d ----
    {
        float2 A  = make_float2(1.f, 1.f);
        float2 Bc = make_float2(0.f, 0.f);
        float2 buf[4];
#pragma unroll
        for (int k = 0; k < 4; k++) buf[k] = ip[k*(DD/2)];
#pragma unroll 4
        for (int t = 0; t < CH; t++) {
            float2 in = buf[t & 3];
            if (t + 4 < CH) buf[t & 3] = ip[(t + 4)*(DD/2)];
            float kx = fmaf(0.5f, in.x, INV_TAU);
            float ky = fmaf(0.5f, in.y, INV_TAU);
            float ex = expnk(kx);
            float ey = expnk(ky);
            float rx = __fdividef(INV_TAU, kx);
            float ry = __fdividef(INV_TAU, ky);
            float bx = fmaf(-rx, ex, rx);
            float by = fmaf(-ry, ey, ry);
            A.x *= ex;  A.y *= ey;
            Bc.x = fmaf(ex, Bc.x, bx);
            Bc.y = fmaf(ey, Bc.y, by);
        }
        *reinterpret_cast<float2*>(&Asm[w][2*lane]) = A;
        *reinterpret_cast<float2*>(&Bsm[w][2*lane]) = Bc;
    }
    __syncthreads();

    // ---- phase 2: exclusive block scan over 8 chunks ----
    if (tid < DD) {
        float s = syn_x0[b*DD + tid];
#pragma unroll
        for (int c = 0; c < NW; c++) {
            Ssm[c][tid] = s;
            s = fmaf(Asm[c][tid], s, Bsm[c][tid]);
        }
    }
    __syncthreads();

    // ---- phase 3: re-stream, emit x_cat + xw ----
    float2 s = *reinterpret_cast<float2*>(&Ssm[w][2*lane]);
    float2* xc = reinterpret_cast<float2*>(out_xcat)
                 + ((size_t)b*TT + t0)*DD + lane;
    float* xwp = g_xw + ((size_t)b*TT + t0)*HH;

    float2 buf[4];
#pragma unroll
    for (int k = 0; k < 4; k++) buf[k] = ip[k*(DD/2)];

#pragma unroll 4
    for (int t = 0; t < CH; t++) {
        float2 in = buf[t & 3];
        if (t + 4 < CH) buf[t & 3] = ip[(t + 4)*(DD/2)];

        float kx = fmaf(0.5f, in.x, INV_TAU);
        float ky = fmaf(0.5f, in.y, INV_TAU);
        float ex = expnk(kx);
        float ey = expnk(ky);
        float rx = __fdividef(INV_TAU, kx);
        float ry = __fdividef(INV_TAU, ky);

        float2 sx;
        sx.x = s.x * in.x;
        sx.y = s.y * in.y;

        xc[t*DD]      = in;
        xc[t*DD + 32] = sx;

        float bx = fmaf(-rx, ex, rx);
        float by = fmaf(-ry, ey, ry);
        s.x = fmaf(ex, s.x, bx);
        s.y = fmaf(ey, s.y, by);

        // slot i accumulates h-pair (i ^ sig) over this lane's 2 d's
        u64 dx0 = pk2(in.x, in.x);
        u64 dx1 = pk2(in.y, in.y);
        u64 ds0 = pk2(sx.x, sx.x);
        u64 ds1 = pk2(sx.y, sx.y);
        u64 acc[8];
#pragma unroll
        for (int i = 0; i < 8; i++) {
            u64 a = mul2(dx0, wa0[i]);
            a = fma2(dx1, wa1[i], a);
            a = fma2(ds0, wb0[i], a);
            a = fma2(ds1, wb1[i], a);
            acc[i] = a;
        }

        // select-free butterfly: plain shfl_xor + add2 at every stage
#pragma unroll
        for (int i = 0; i < 4; i++)
            acc[i] = add2(acc[i], __shfl_xor_sync(0xffffffffu, acc[i + 4], 1));
#pragma unroll
        for (int i = 0; i < 2; i++)
            acc[i] = add2(acc[i], __shfl_xor_sync(0xffffffffu, acc[i + 2], 2));
        acc[0] = add2(acc[0], __shfl_xor_sync(0xffffffffu, acc[1], 4));
        acc[0] = add2(acc[0], __shfl_xor_sync(0xffffffffu, acc[0], 8));
        acc[0] = add2(acc[0], __shfl_xor_sync(0xffffffffu, acc[0], 16));

        // lane l (<8) holds complete h-pair sig(l): store u64 (coalesced 64B)
        if (lane < 8)
            *reinterpret_cast<u64*>(&xwp[t*HH + 2*sig]) = acc[0];
    }
}

// ============================================================================
// K2: sequential ReLU RNN + hidden + output. 2 batches per warp.
// Half-warp = batch, lane = h-index j. Per-lane-src shfl serves both batches.
// t-loop unrolled by 8 so the prefetch ring stays in registers.
// ============================================================================
__global__ void __launch_bounds__(32) k2_rnn(
    const float* __restrict__ h0,       // [B,16]
    const float* __restrict__ w_hh,     // [16,16]
    const float* __restrict__ bias,     // [16]
    const float* __restrict__ lin_w,    // [16]
    const float* __restrict__ lin_b,    // [1]
    float* __restrict__ out_output,     // [B,T]
    float* __restrict__ out_hidden)     // [B,T,16]
{
    const int lane = threadIdx.x;
    const int j    = lane & 15;
    const int base = lane & 16;          // src base for this half's broadcasts
    const int b    = blockIdx.x * 2 + (lane >> 4);

    float wj[HH], lw[HH];
#pragma unroll
    for (int i = 0; i < HH; i++) {
        wj[i] = w_hh[i*HH + j];
        lw[i] = lin_w[i];
    }
    const float biasj = bias[j];
    const float lb    = lin_b[0];

    float h = h0[b*HH + j];              // lane holds h[j] of its batch

    const float* xp = g_xw + (size_t)b*TT*HH + j;
    float*      hid = out_hidden + (size_t)b*TT*HH + j;
    float*       op = out_output + (size_t)b*TT;

    float buf[8];
#pragma unroll
    for (int p = 0; p < 8; p++) buf[p] = xp[p*HH];

#pragma unroll 8
    for (int t = 0; t < TT; t++) {
        float xwv = buf[t & 7];
        if (t + 8 < TT) buf[t & 7] = xp[(t + 8)*HH];

        // broadcast h_{t-1} of this half's batch: per-lane src lane
        float hb[HH];
#pragma unroll
        for (int i = 0; i < HH; i++)
            hb[i] = __shfl_sync(0xffffffffu, h, base + i);

        // matvec (two chains)
        float a0 = xwv + biasj, a1 = 0.0f;
#pragma unroll
        for (int i = 0; i < HH; i += 2) {
            a0 = fmaf(hb[i],     wj[i],     a0);
            a1 = fmaf(hb[i + 1], wj[i + 1], a1);
        }
        h = fmaxf(a0 + a1, 0.0f);

        hid[t*HH] = h;                   // both halves store their batch

        // output for step t-1 (local dot of hb = h_{t-1})
        float v0 = 0.0f, v1 = 0.0f;
#pragma unroll
        for (int i = 0; i < HH; i += 2) {
            v0 = fmaf(hb[i],     lw[i],     v0);
            v1 = fmaf(hb[i + 1], lw[i + 1], v1);
        }
        if (j == 0 && t > 0) op[t - 1] = v0 + v1 + lb;
    }

    // epilogue: output for t = TT-1
    {
        float hb[HH];
#pragma unroll
        for (int i = 0; i < HH; i++)
            hb[i] = __shfl_sync(0xffffffffu, h, base + i);
        float v0 = 0.0f, v1 = 0.0f;
#pragma unroll
        for (int i = 0; i < HH; i += 2) {
            v0 = fmaf(hb[i],     lw[i],     v0);
            v1 = fmaf(hb[i + 1], lw[i + 1], v1);
        }
        if (j == 0) op[TT - 1] = v0 + v1 + lb;
    }
}

extern "C" void kernel_launch(void* const* d_in, const int* in_sizes, int n_in,
                              void* d_out, int out_size) {
    const float* inputs = (const float*)d_in[0];   // [B,T,64]
    const float* syn_x0 = (const float*)d_in[1];   // [B,64]
    const float* h0     = (const float*)d_in[2];   // [B,16]
    const float* w_ih   = (const float*)d_in[3];   // [128,16]
    const float* w_hh   = (const float*)d_in[4];   // [16,16]
    const float* bias   = (const float*)d_in[5];   // [16]
    const float* lin_w  = (const float*)d_in[6];   // [16,1]
    const float* lin_b  = (const float*)d_in[7];   // [1]

    float* out = (float*)d_out;
    // tuple concat order: output [B,T,1], hidden [B,T,16], x_cat [B,T,128]
    float* out_output = out;
    float* out_hidden = out + (size_t)BB*TT;
    float* out_xcat   = out + (size_t)BB*TT + (size_t)BB*TT*HH;

    k1_syn_proj<<<BB, 256>>>(inputs, syn_x0, w_ih, out_xcat);
    k2_rnn<<<BB/2, 32>>>(h0, w_hh, bias, lin_w, lin_b, out_output, out_hidden);
}

// round 15
// speedup vs baseline: 2.4913x; 1.3059x over previous
#include <cuda_runtime.h>

#define BB 2048
#define TT 1024
#define DD 64
#define HH 16
#define CH 256             // timesteps per K1 warp (4 warps per batch)
#define WU 96              // warmup steps: decay exp(-96/6) ~ 1.1e-7
#define INV_TAU (1.0f/6.0f)

typedef unsigned long long u64;

// xw scratch: [B, T, 16]
__device__ float g_xw[(size_t)BB * TT * HH];

__device__ __forceinline__ u64 pk2(float lo, float hi) {
    u64 r; asm("mov.b64 %0, {%1,%2};" : "=l"(r) : "f"(lo), "f"(hi)); return r;
}
__device__ __forceinline__ void unpk2(u64 a, float& lo, float& hi) {
    asm("mov.b64 {%0,%1}, %2;" : "=f"(lo), "=f"(hi) : "l"(a));
}
__device__ __forceinline__ u64 mul2(u64 a, u64 b) {
    u64 r; asm("mul.rn.f32x2 %0, %1, %2;" : "=l"(r) : "l"(a), "l"(b)); return r;
}
__device__ __forceinline__ u64 fma2(u64 a, u64 b, u64 c) {
    u64 r; asm("fma.rn.f32x2 %0, %1, %2, %3;" : "=l"(r) : "l"(a), "l"(b), "l"(c)); return r;
}
__device__ __forceinline__ u64 add2(u64 a, u64 b) {
    u64 r; asm("add.rn.f32x2 %0, %1, %2;" : "=l"(r) : "l"(a), "l"(b)); return r;
}
__device__ __forceinline__ u64 sub2(u64 a, u64 b) {
    u64 r; asm("sub.rn.f32x2 %0, %1, %2;" : "=l"(r) : "l"(a), "l"(b)); return r;
}
__device__ __forceinline__ float frcp(float x) {
    float r; asm("rcp.approx.f32 %0, %1;" : "=f"(r) : "f"(x)); return r;
}

// exp(-5/12) for the centered degree-5 exp(-k) poly (k in [1/6, 2/3), err ~4e-7)
#define EXPC 0.6592406302004438f

// ============================================================================
// K1: warmup-based synaptic state + x_cat + input projection -> g_xw
// Block = 128 threads (4 warps) = one batch. Warp w owns t in [256w, 256w+256).
// Warp 0 starts from exact syn_x0; warps 1-3 warm up over the preceding 96
// steps from s=1 (contraction exp(-96/6) ~ 1e-7 kills the init error).
// Lane owns d-pair (2l, 2l+1); packed-f32x2 syn math; select-free XOR-permuted
// butterfly; lanes 0-7 store one xw h-pair each (coalesced 64B).
// ============================================================================
__global__ void __launch_bounds__(128, 4) k1_syn_proj(
    const float* __restrict__ inputs,   // [B,T,64]
    const float* __restrict__ syn_x0,   // [B,64]
    const float* __restrict__ w_ih,     // [128,16]
    float* __restrict__ out_xcat)       // [B,T,128]
{
    __shared__ float wsm[2*DD][HH];     // raw copy of w_ih

    const int b    = blockIdx.x;
    const int tid  = threadIdx.x;
    const int w    = tid >> 5;
    const int lane = tid & 31;
    const int t0   = w * CH;
    // slot permutation: sig(l^1)=sig^4, sig(l^2)=sig^2, sig(l^4)=sig^1
    const int sig  = ((lane & 1) << 2) | (lane & 2) | ((lane >> 2) & 1);

    {
        const float4* src = reinterpret_cast<const float4*>(w_ih);
        float4* dst = reinterpret_cast<float4*>(&wsm[0][0]);
        for (int i = tid; i < 2*DD*HH/4; i += 128) dst[i] = src[i];
    }
    __syncthreads();

    // slot i holds weights for h-pair p = i ^ sig
    u64 wa0[8], wa1[8], wb0[8], wb1[8];
#pragma unroll
    for (int i = 0; i < 8; i++) {
        const int p = i ^ sig;
        wa0[i] = *reinterpret_cast<const u64*>(&wsm[2*lane   ][2*p]);
        wa1[i] = *reinterpret_cast<const u64*>(&wsm[2*lane+1 ][2*p]);
        wb0[i] = *reinterpret_cast<const u64*>(&wsm[64+2*lane][2*p]);
        wb1[i] = *reinterpret_cast<const u64*>(&wsm[65+2*lane][2*p]);
    }

    // packed constants
    const u64 HALF2 = pk2(0.5f, 0.5f);
    const u64 TAU2  = pk2(INV_TAU, INV_TAU);
    const u64 CTR2  = pk2(0.4166666666666667f, 0.4166666666666667f);
    const u64 P5 = pk2(-EXPC/120.0f, -EXPC/120.0f);
    const u64 P4 = pk2( EXPC/24.0f,   EXPC/24.0f);
    const u64 P3 = pk2(-EXPC/6.0f,   -EXPC/6.0f);
    const u64 P2 = pk2( EXPC*0.5f,    EXPC*0.5f);
    const u64 P1 = pk2(-EXPC,        -EXPC);
    const u64 P0 = pk2( EXPC,         EXPC);

    // ---- synaptic state init ----
    u64 s2;
    if (w == 0) {
        float2 s0v = *reinterpret_cast<const float2*>(&syn_x0[b*DD + 2*lane]);
        s2 = pk2(s0v.x, s0v.y);
    } else {
        s2 = pk2(1.0f, 1.0f);
        const float2* wp = reinterpret_cast<const float2*>(inputs)
                           + ((size_t)b*TT + t0 - WU)*(DD/2) + lane;
        float2 wbuf[4];
#pragma unroll
        for (int k = 0; k < 4; k++) wbuf[k] = wp[k*(DD/2)];
#pragma unroll 4
        for (int t = 0; t < WU; t++) {
            float2 in = wbuf[t & 3];
            if (t + 4 < WU) wbuf[t & 3] = wp[(t + 4)*(DD/2)];
            u64 in64 = pk2(in.x, in.y);
            u64 k2 = fma2(in64, HALF2, TAU2);
            u64 x2 = sub2(k2, CTR2);
            u64 e2 = fma2(P5, x2, P4);
            e2 = fma2(e2, x2, P3);
            e2 = fma2(e2, x2, P2);
            e2 = fma2(e2, x2, P1);
            e2 = fma2(e2, x2, P0);
            float kx, ky; unpk2(k2, kx, ky);
            u64 r2 = mul2(pk2(frcp(kx), frcp(ky)), TAU2);
            u64 b2 = sub2(r2, mul2(r2, e2));
            s2 = fma2(e2, s2, b2);
        }
    }

    // ---- main loop: emit x_cat + xw ----
    const float2* ip = reinterpret_cast<const float2*>(inputs)
                       + ((size_t)b*TT + t0)*(DD/2) + lane;
    float2* xc = reinterpret_cast<float2*>(out_xcat)
                 + ((size_t)b*TT + t0)*DD + lane;
    float* xwp = g_xw + ((size_t)b*TT + t0)*HH;

    float2 buf[4];
#pragma unroll
    for (int k = 0; k < 4; k++) buf[k] = ip[k*(DD/2)];

#pragma unroll 4
    for (int t = 0; t < CH; t++) {
        float2 in = buf[t & 3];
        if (t + 4 < CH) buf[t & 3] = ip[(t + 4)*(DD/2)];

        // ---- packed syn: e = poly(k), r = tau/k, sx = s*in, s' = e*s + r(1-e)
        u64 in64 = pk2(in.x, in.y);
        u64 k2 = fma2(in64, HALF2, TAU2);
        u64 x2 = sub2(k2, CTR2);
        u64 e2 = fma2(P5, x2, P4);
        e2 = fma2(e2, x2, P3);
        e2 = fma2(e2, x2, P2);
        e2 = fma2(e2, x2, P1);
        e2 = fma2(e2, x2, P0);
        float kx, ky; unpk2(k2, kx, ky);
        u64 r2 = mul2(pk2(frcp(kx), frcp(ky)), TAU2);

        u64 sx2 = mul2(s2, in64);        // syn(pre-update) * input

        xc[t*DD] = in;                                        // x_cat[:, :64]
        *reinterpret_cast<u64*>(xc + t*DD + 32) = sx2;        // x_cat[:, 64:]

        u64 b2 = sub2(r2, mul2(r2, e2));
        s2 = fma2(e2, s2, b2);

        // ---- proj partials: slot i accumulates h-pair (i ^ sig) ----
        float sxx, sxy; unpk2(sx2, sxx, sxy);
        u64 dx0 = pk2(in.x, in.x);
        u64 dx1 = pk2(in.y, in.y);
        u64 ds0 = pk2(sxx, sxx);
        u64 ds1 = pk2(sxy, sxy);
        u64 acc[8];
#pragma unroll
        for (int i = 0; i < 8; i++) {
            u64 a = mul2(dx0, wa0[i]);
            a = fma2(dx1, wa1[i], a);
            a = fma2(ds0, wb0[i], a);
            a = fma2(ds1, wb1[i], a);
            acc[i] = a;
        }

        // ---- select-free butterfly: plain shfl_xor + add2 at every stage ----
#pragma unroll
        for (int i = 0; i < 4; i++)
            acc[i] = add2(acc[i], __shfl_xor_sync(0xffffffffu, acc[i + 4], 1));
#pragma unroll
        for (int i = 0; i < 2; i++)
            acc[i] = add2(acc[i], __shfl_xor_sync(0xffffffffu, acc[i + 2], 2));
        acc[0] = add2(acc[0], __shfl_xor_sync(0xffffffffu, acc[1], 4));
        acc[0] = add2(acc[0], __shfl_xor_sync(0xffffffffu, acc[0], 8));
        acc[0] = add2(acc[0], __shfl_xor_sync(0xffffffffu, acc[0], 16));

        // lane l (<8) holds complete h-pair sig(l): store u64 (coalesced 64B)
        if (lane < 8)
            *reinterpret_cast<u64*>(&xwp[t*HH + 2*sig]) = acc[0];
    }
}

// ============================================================================
// K2: sequential ReLU RNN + hidden + output. 2 batches per warp. (R10 version)
// ============================================================================
__global__ void __launch_bounds__(32) k2_rnn(
    const float* __restrict__ h0,       // [B,16]
    const float* __restrict__ w_hh,     // [16,16]
    const float* __restrict__ bias,     // [16]
    const float* __restrict__ lin_w,    // [16]
    const float* __restrict__ lin_b,    // [1]
    float* __restrict__ out_output,     // [B,T]
    float* __restrict__ out_hidden)     // [B,T,16]
{
    const int lane = threadIdx.x;
    const int j    = lane & 15;
    const int base = lane & 16;          // src base for this half's broadcasts
    const int b    = blockIdx.x * 2 + (lane >> 4);

    float wj[HH], lw[HH];
#pragma unroll
    for (int i = 0; i < HH; i++) {
        wj[i] = w_hh[i*HH + j];
        lw[i] = lin_w[i];
    }
    const float biasj = bias[j];
    const float lb    = lin_b[0];

    float h = h0[b*HH + j];              // lane holds h[j] of its batch

    const float* xp = g_xw + (size_t)b*TT*HH + j;
    float*      hid = out_hidden + (size_t)b*TT*HH + j;
    float*       op = out_output + (size_t)b*TT;

    float buf[8];
#pragma unroll
    for (int p = 0; p < 8; p++) buf[p] = xp[p*HH];

#pragma unroll 8
    for (int t = 0; t < TT; t++) {
        float xwv = buf[t & 7];
        if (t + 8 < TT) buf[t & 7] = xp[(t + 8)*HH];

        // broadcast h_{t-1} of this half's batch: per-lane src lane
        float hb[HH];
#pragma unroll
        for (int i = 0; i < HH; i++)
            hb[i] = __shfl_sync(0xffffffffu, h, base + i);

        // matvec (two chains)
        float a0 = xwv + biasj, a1 = 0.0f;
#pragma unroll
        for (int i = 0; i < HH; i += 2) {
            a0 = fmaf(hb[i],     wj[i],     a0);
            a1 = fmaf(hb[i + 1], wj[i + 1], a1);
        }
        h = fmaxf(a0 + a1, 0.0f);

        hid[t*HH] = h;                   // both halves store their batch

        // output for step t-1 (local dot of hb = h_{t-1})
        float v0 = 0.0f, v1 = 0.0f;
#pragma unroll
        for (int i = 0; i < HH; i += 2) {
            v0 = fmaf(hb[i],     lw[i],     v0);
            v1 = fmaf(hb[i + 1], lw[i + 1], v1);
        }
        if (j == 0 && t > 0) op[t - 1] = v0 + v1 + lb;
    }

    // epilogue: output for t = TT-1
    {
        float hb[HH];
#pragma unroll
        for (int i = 0; i < HH; i++)
            hb[i] = __shfl_sync(0xffffffffu, h, base + i);
        float v0 = 0.0f, v1 = 0.0f;
#pragma unroll
        for (int i = 0; i < HH; i += 2) {
            v0 = fmaf(hb[i],     lw[i],     v0);
            v1 = fmaf(hb[i + 1], lw[i + 1], v1);
        }
        if (j == 0) op[TT - 1] = v0 + v1 + lb;
    }
}

extern "C" void kernel_launch(void* const* d_in, const int* in_sizes, int n_in,
                              void* d_out, int out_size) {
    const float* inputs = (const float*)d_in[0];   // [B,T,64]
    const float* syn_x0 = (const float*)d_in[1];   // [B,64]
    const float* h0     = (const float*)d_in[2];   // [B,16]
    const float* w_ih   = (const float*)d_in[3];   // [128,16]
    const float* w_hh   = (const float*)d_in[4];   // [16,16]
    const float* bias   = (const float*)d_in[5];   // [16]
    const float* lin_w  = (const float*)d_in[6];   // [16,1]
    const float* lin_b  = (const float*)d_in[7];   // [1]

    float* out = (float*)d_out;
    // tuple concat order: output [B,T,1], hidden [B,T,16], x_cat [B,T,128]
    float* out_output = out;
    float* out_hidden = out + (size_t)BB*TT;
    float* out_xcat   = out + (size_t)BB*TT + (size_t)BB*TT*HH;

    k1_syn_proj<<<BB, 128>>>(inputs, syn_x0, w_ih, out_xcat);
    k2_rnn<<<BB/2, 32>>>(h0, w_hh, bias, lin_w, lin_b, out_output, out_hidden);
}